// round 3
// baseline (speedup 1.0000x reference)
#include <cuda_runtime.h>
#include <mma.h>
#include <math.h>

using namespace nvcuda;

#define GRIDN 16
#define NN 256
#define DD 64
#define BB 4096
#define FF 512
#define HH 16384
#define CC 1000
#define CPAD 1024

// ---------------- scratch ----------------------------------------------------
__device__ float g_nodes[(size_t)BB * HH];     // 256 MB (agg, post-fold)
__device__ float g_win2[(size_t)HH * FF];      // 32 MB  (adj-folded W_in)
__device__ float g_bin2[HH];                   // folded b_in
__device__ float g_w[(size_t)BB * CPAD];       // softmax weights, 4/node
__device__ float g_mmat[(size_t)CC * CPAD];    // folded basis x W_out
__device__ float g_adjw[NN * 4];
__device__ int   g_adjn[NN * 4];
__device__ float g_K[4 * DD];

__device__ __forceinline__ float sigmoidf_(float x) { return 1.0f / (1.0f + expf(-x)); }
__device__ __forceinline__ float clip3(float x) { return fminf(fmaxf(x, -3.0f), 3.0f); }

// ---------------- prep: adjacency rows + K = basis @ k_w^T + k_b ------------
__global__ void prep_kernel(const float* __restrict__ adjw,
                            const float* __restrict__ k_w,
                            const float* __restrict__ k_b,
                            const float* __restrict__ basis)
{
    int t = threadIdx.x;
    int r = t >> 4, c = t & 15;
    int nb[4]; int cnt = 0;
    if (r > 0)         nb[cnt++] = t - GRIDN;
    if (r < GRIDN - 1) nb[cnt++] = t + GRIDN;
    if (c > 0)         nb[cnt++] = t - 1;
    if (c < GRIDN - 1) nb[cnt++] = t + 1;

    float w[4] = {0.f, 0.f, 0.f, 0.f};
    float deg = 0.f;
    for (int j = 0; j < cnt; j++) { w[j] = sigmoidf_(adjw[t * NN + nb[j]]); deg += w[j]; }
    deg = fmaxf(deg, 1e-6f);
    int over = 0;
    for (int j = 0; j < cnt; j++) { w[j] /= deg; if (w[j] > 0.1f) over++; }
    if (over < 1) w[0] = fmaxf(w[0], 0.5f);
    for (int j = 0; j < 4; j++) {
        g_adjw[t * 4 + j] = (j < cnt) ? w[j] : 0.f;
        g_adjn[t * 4 + j] = (j < cnt) ? nb[j] : t;
    }

    int kr = t >> 6, kc = t & 63;
    float acc = k_b[kc];
    for (int d = 0; d < DD; d++) acc += basis[kr * DD + d] * k_w[kc * DD + d];
    g_K[kr * DD + kc] = acc;
}

// ---------------- fold adjacency into W_in / b_in ----------------------------
// g_win2[n*64+d, f] = sum_j adjw[n,j] * W_in[nb_j*64+d, f]
__global__ void fold_win_kernel(const float* __restrict__ W_in, const float* __restrict__ b_in)
{
    int idx = blockIdx.x * blockDim.x + threadIdx.x;   // over 16384 * 128 float4
    if (idx >= HH * (FF / 4)) return;
    int row = idx >> 7, c4 = idx & 127;
    int n = row >> 6, d = row & 63;
    float w0 = g_adjw[n * 4 + 0], w1 = g_adjw[n * 4 + 1];
    float w2 = g_adjw[n * 4 + 2], w3 = g_adjw[n * 4 + 3];
    int   r0 = g_adjn[n * 4 + 0] * DD + d, r1 = g_adjn[n * 4 + 1] * DD + d;
    int   r2 = g_adjn[n * 4 + 2] * DD + d, r3 = g_adjn[n * 4 + 3] * DD + d;
    float4 a = ((const float4*)(W_in + (size_t)r0 * FF))[c4];
    float4 b = ((const float4*)(W_in + (size_t)r1 * FF))[c4];
    float4 c = ((const float4*)(W_in + (size_t)r2 * FF))[c4];
    float4 e = ((const float4*)(W_in + (size_t)r3 * FF))[c4];
    float4 o;
    o.x = w0 * a.x + w1 * b.x + w2 * c.x + w3 * e.x;
    o.y = w0 * a.y + w1 * b.y + w2 * c.y + w3 * e.y;
    o.z = w0 * a.z + w1 * b.z + w2 * c.z + w3 * e.z;
    o.w = w0 * a.w + w1 * b.w + w2 * c.w + w3 * e.w;
    ((float4*)(g_win2 + (size_t)row * FF))[c4] = o;
    if (c4 == 0)
        g_bin2[row] = w0 * b_in[r0] + w1 * b_in[r1] + w2 * b_in[r2] + w3 * b_in[r3];
}

// ---------------- Mmat[c, n*4+j] = sum_d basis[j,d] * W_out[c, n*64+d] ------
__global__ void mmat_kernel(const float* __restrict__ W_out, const float* __restrict__ basis)
{
    int gw = (blockIdx.x * blockDim.x + threadIdx.x) >> 5;
    int lane = threadIdx.x & 31;
    if (gw >= CC * NN) return;
    const float* row = W_out + (size_t)gw * DD;
    float v0 = row[lane], v1 = row[lane + 32];
    float r0 = v0 * basis[       lane] + v1 * basis[       lane + 32];
    float r1 = v0 * basis[ 64 +  lane] + v1 * basis[ 64 +  lane + 32];
    float r2 = v0 * basis[128 +  lane] + v1 * basis[128 +  lane + 32];
    float r3 = v0 * basis[192 +  lane] + v1 * basis[192 +  lane + 32];
    #pragma unroll
    for (int o = 16; o; o >>= 1) {
        r0 += __shfl_xor_sync(0xffffffffu, r0, o);
        r1 += __shfl_xor_sync(0xffffffffu, r1, o);
        r2 += __shfl_xor_sync(0xffffffffu, r2, o);
        r3 += __shfl_xor_sync(0xffffffffu, r3, o);
    }
    if (lane == 0) ((float4*)g_mmat)[gw] = make_float4(r0, r1, r2, r3);
}

// ---------------- pipelined NT GEMM (tf32, cp.async 3-stage) ----------------
#define BM 128
#define BN 128
#define BK 32
#define GLDS 36
#define GSTAGE 3
#define GSTRIDE ((BM + BN) * GLDS)
#define GEMM_SMEM (GSTAGE * GSTRIDE * 4)           // 110592 B

__device__ __forceinline__ void g_issue(const float* A, const float* B, float* sm,
                                        int t, int m0, int n0, int K, int Nvalid,
                                        int kt, int s)
{
    int k0 = kt * BK;
    float* dstA0 = sm + s * GSTRIDE;
    float* dstB0 = dstA0 + BM * GLDS;
    #pragma unroll
    for (int i = 0; i < 4; i++) {
        int id = t + i * 256;
        int row = id >> 3, c4 = id & 7;
        const float* gA = A + (size_t)(m0 + row) * K + k0 + c4 * 4;
        unsigned int da = (unsigned int)__cvta_generic_to_shared(dstA0 + row * GLDS + c4 * 4);
        asm volatile("cp.async.cg.shared.global [%0], [%1], 16;\n" :: "r"(da), "l"(gA));
        int brow = n0 + row;
        const float* gB = B + (size_t)brow * K + k0 + c4 * 4;
        unsigned int db = (unsigned int)__cvta_generic_to_shared(dstB0 + row * GLDS + c4 * 4);
        int sz = (brow < Nvalid) ? 16 : 0;
        asm volatile("cp.async.cg.shared.global [%0], [%1], 16, %2;\n" :: "r"(db), "l"(gB), "r"(sz));
    }
    asm volatile("cp.async.commit_group;\n" ::: "memory");
}

template<bool STORE_OUT>
__global__ __launch_bounds__(256, 2) void gemm_nt_pipe(
    const float* __restrict__ A, const float* __restrict__ B, float* __restrict__ C,
    int M, int Nvalid, int K, int ldc, const float* __restrict__ bias)
{
    extern __shared__ float sm[];
    int t = threadIdx.x;
    int m0 = blockIdx.y * BM, n0 = blockIdx.x * BN;
    int w = t >> 5, wm = w & 1, wn = w >> 1;
    int KT = K / BK;

    wmma::fragment<wmma::accumulator, 16, 16, 8, float> acc[4][2];
    #pragma unroll
    for (int i = 0; i < 4; i++)
        #pragma unroll
        for (int j = 0; j < 2; j++) wmma::fill_fragment(acc[i][j], 0.0f);

    g_issue(A, B, sm, t, m0, n0, K, Nvalid, 0, 0);
    g_issue(A, B, sm, t, m0, n0, K, Nvalid, 1, 1);

    for (int kt = 0; kt < KT; kt++) {
        asm volatile("cp.async.wait_group 1;\n" ::: "memory");
        __syncthreads();
        if (kt + 2 < KT)
            g_issue(A, B, sm, t, m0, n0, K, Nvalid, kt + 2, (kt + 2) % GSTAGE);

        const float* sa = sm + (kt % GSTAGE) * GSTRIDE;
        const float* sb = sa + BM * GLDS;
        #pragma unroll
        for (int kk = 0; kk < BK / 8; kk++) {
            wmma::fragment<wmma::matrix_a, 16, 16, 8, wmma::precision::tf32, wmma::row_major> af[4];
            wmma::fragment<wmma::matrix_b, 16, 16, 8, wmma::precision::tf32, wmma::col_major> bf[2];
            #pragma unroll
            for (int i = 0; i < 4; i++) {
                wmma::load_matrix_sync(af[i], sa + (wm * 64 + i * 16) * GLDS + kk * 8, GLDS);
                #pragma unroll
                for (int e = 0; e < af[i].num_elements; e++)
                    af[i].x[e] = wmma::__float_to_tf32(af[i].x[e]);
            }
            #pragma unroll
            for (int j = 0; j < 2; j++) {
                wmma::load_matrix_sync(bf[j], sb + (wn * 32 + j * 16) * GLDS + kk * 8, GLDS);
                #pragma unroll
                for (int e = 0; e < bf[j].num_elements; e++)
                    bf[j].x[e] = wmma::__float_to_tf32(bf[j].x[e]);
            }
            #pragma unroll
            for (int i = 0; i < 4; i++)
                #pragma unroll
                for (int j = 0; j < 2; j++)
                    wmma::mma_sync(acc[i][j], af[i], bf[j], acc[i][j]);
        }
    }

    if (STORE_OUT) {
        // stage tile in smem, then guarded writes with fused bias
        __syncthreads();
        float* tile = sm;   // 128 x 132
        #pragma unroll
        for (int i = 0; i < 4; i++)
            #pragma unroll
            for (int j = 0; j < 2; j++)
                wmma::store_matrix_sync(tile + (wm * 64 + i * 16) * 132 + wn * 32 + j * 16,
                                        acc[i][j], 132, wmma::mem_row_major);
        __syncthreads();
        for (int idx = t; idx < BM * BN; idx += 256) {
            int r = idx >> 7, c = idx & 127;
            int col = n0 + c;
            if (col < Nvalid)
                C[(size_t)(m0 + r) * ldc + col] = tile[r * 132 + c] + bias[col];
        }
    } else {
        #pragma unroll
        for (int i = 0; i < 4; i++)
            #pragma unroll
            for (int j = 0; j < 2; j++)
                wmma::store_matrix_sync(C + (size_t)(m0 + wm * 64 + i * 16) * ldc + n0 + wn * 32 + j * 16,
                                        acc[i][j], ldc, wmma::mem_row_major);
    }
}

// ---------------- fused middle v2: one CTA per batch element -----------------
#define MLD 68
constexpr int MID_SMEM_FLOATS = 256 * MLD * 2 + 64 * MLD * 3 + 256 + 256 + 64 + 64;
constexpr int MID_SMEM_BYTES  = MID_SMEM_FLOATS * 4;   // ~194 KB

__global__ __launch_bounds__(256) void middle_kernel(
    const float* __restrict__ V_slow, const float* __restrict__ sem_mem,
    const float* __restrict__ mix_w, const float* __restrict__ mix_b,
    const float* __restrict__ q_w, const float* __restrict__ q_b)
{
    extern __shared__ float smem_[];
    float* sA   = smem_;               // 256*68 (v, later cell_out)
    float* sB   = sA + 256 * MLD;      // 256*68 (agg, y_pred, v_pred, Q)
    float* sV   = sB + 256 * MLD;      // 64*68
    float* sS   = sV + 64 * MLD;       // 64*68
    float* sQm  = sS + 64 * MLD;       // 64*68
    float* smix = sQm + 64 * MLD;      // 256
    float* sKb  = smix + 256;          // 256
    float* sqb  = sKb + 256;           // 64
    float* smw  = sqb + 64;            // 64

    int b = blockIdx.x;
    int t = threadIdx.x;
    int lane = t & 31;

    // weights (lane = channel -> conflict-free STS)
    for (int i = t; i < 64 * 64; i += 256) {
        int r = i >> 6, c2 = i & 63;
        sV[r * MLD + c2]  = wmma::__float_to_tf32(V_slow[i]);
        sS[r * MLD + c2]  = wmma::__float_to_tf32(sem_mem[i]);
        sQm[r * MLD + c2] = wmma::__float_to_tf32(q_w[i]);
    }
    if (t < 64) { sqb[t] = q_b[t]; smw[t] = mix_w[t]; }
    sKb[t] = g_K[t];

    // agg (already adjacency-folded) + bias -> sB (tf32)
    {
        const float4* np_ = (const float4*)(g_nodes + (size_t)b * HH);
        const float4* bp_ = (const float4*)g_bin2;
        for (int i = t; i < HH / 4; i += 256) {
            float4 v = np_[i], bb = bp_[i];
            int n = i >> 4, d = (i & 15) << 2;
            float* dst = &sB[n * MLD + d];
            dst[0] = wmma::__float_to_tf32(v.x + bb.x);
            dst[1] = wmma::__float_to_tf32(v.y + bb.y);
            dst[2] = wmma::__float_to_tf32(v.z + bb.z);
            dst[3] = wmma::__float_to_tf32(v.w + bb.w);
        }
    }
    __syncthreads();

    int w = t >> 5;
    int r0w = w * 32;

    typedef wmma::fragment<wmma::matrix_a, 16, 16, 8, wmma::precision::tf32, wmma::row_major> AFrag;
    typedef wmma::fragment<wmma::matrix_b, 16, 16, 8, wmma::precision::tf32, wmma::col_major> BFrag;
    typedef wmma::fragment<wmma::accumulator, 16, 16, 8, float> CFrag;

    // pass A: v = clip(agg @ V^T) -> sA (fp32); own rows only, no sync needed
    {
        CFrag vf[2][4];
        #pragma unroll
        for (int i = 0; i < 2; i++)
            #pragma unroll
            for (int j = 0; j < 4; j++) wmma::fill_fragment(vf[i][j], 0.f);
        #pragma unroll
        for (int kk = 0; kk < 8; kk++) {
            AFrag af[2]; BFrag bv[4];
            #pragma unroll
            for (int i = 0; i < 2; i++) wmma::load_matrix_sync(af[i], &sB[(r0w + i * 16) * MLD + kk * 8], MLD);
            #pragma unroll
            for (int j = 0; j < 4; j++) wmma::load_matrix_sync(bv[j], &sV[(j * 16) * MLD + kk * 8], MLD);
            #pragma unroll
            for (int i = 0; i < 2; i++)
                #pragma unroll
                for (int j = 0; j < 4; j++) wmma::mma_sync(vf[i][j], af[i], bv[j], vf[i][j]);
        }
        #pragma unroll
        for (int i = 0; i < 2; i++)
            #pragma unroll
            for (int j = 0; j < 4; j++) {
                #pragma unroll
                for (int e = 0; e < 8; e++) vf[i][j].x[e] = clip3(vf[i][j].x[e]);
                wmma::store_matrix_sync(&sA[(r0w + i * 16) * MLD + j * 16], vf[i][j], MLD, wmma::mem_row_major);
            }
    }
    // pass B: y_pred = tf32(clip(agg @ S^T)) -> sB (own rows)
    {
        CFrag yf[2][4];
        #pragma unroll
        for (int i = 0; i < 2; i++)
            #pragma unroll
            for (int j = 0; j < 4; j++) wmma::fill_fragment(yf[i][j], 0.f);
        #pragma unroll
        for (int kk = 0; kk < 8; kk++) {
            AFrag af[2]; BFrag bs[4];
            #pragma unroll
            for (int i = 0; i < 2; i++) wmma::load_matrix_sync(af[i], &sB[(r0w + i * 16) * MLD + kk * 8], MLD);
            #pragma unroll
            for (int j = 0; j < 4; j++) wmma::load_matrix_sync(bs[j], &sS[(j * 16) * MLD + kk * 8], MLD);
            #pragma unroll
            for (int i = 0; i < 2; i++)
                #pragma unroll
                for (int j = 0; j < 4; j++) wmma::mma_sync(yf[i][j], af[i], bs[j], yf[i][j]);
        }
        #pragma unroll
        for (int i = 0; i < 2; i++)
            #pragma unroll
            for (int j = 0; j < 4; j++) {
                #pragma unroll
                for (int e = 0; e < 8; e++) yf[i][j].x[e] = wmma::__float_to_tf32(clip3(yf[i][j].x[e]));
                wmma::store_matrix_sync(&sB[(r0w + i * 16) * MLD + j * 16], yf[i][j], MLD, wmma::mem_row_major);
            }
    }
    __syncthreads();

    // mix = sigmoid(v . mix_w + mix_b): warp-per-row, shuffle reduce
    {
        float mb = mix_b[0];
        float w0 = smw[lane], w1 = smw[lane + 32];
        #pragma unroll
        for (int it = 0; it < 32; it++) {
            int n = it * 8 + w;
            float p = sA[n * MLD + lane] * w0 + sA[n * MLD + lane + 32] * w1;
            #pragma unroll
            for (int o = 16; o; o >>= 1) p += __shfl_xor_sync(0xffffffffu, p, o);
            if (lane == 0) smix[n] = sigmoidf_(p + mb);
        }
    }

    // v_pred = clip(y_pred @ V^T) -> sB (own rows)
    {
        CFrag pf[2][4];
        #pragma unroll
        for (int i = 0; i < 2; i++)
            #pragma unroll
            for (int j = 0; j < 4; j++) wmma::fill_fragment(pf[i][j], 0.f);
        #pragma unroll
        for (int kk = 0; kk < 8; kk++) {
            AFrag af[2]; BFrag bv[4];
            #pragma unroll
            for (int i = 0; i < 2; i++) wmma::load_matrix_sync(af[i], &sB[(r0w + i * 16) * MLD + kk * 8], MLD);
            #pragma unroll
            for (int j = 0; j < 4; j++) wmma::load_matrix_sync(bv[j], &sV[(j * 16) * MLD + kk * 8], MLD);
            #pragma unroll
            for (int i = 0; i < 2; i++)
                #pragma unroll
                for (int j = 0; j < 4; j++) wmma::mma_sync(pf[i][j], af[i], bv[j], pf[i][j]);
        }
        #pragma unroll
        for (int i = 0; i < 2; i++)
            #pragma unroll
            for (int j = 0; j < 4; j++) {
                #pragma unroll
                for (int e = 0; e < 8; e++) pf[i][j].x[e] = clip3(pf[i][j].x[e]);
                wmma::store_matrix_sync(&sB[(r0w + i * 16) * MLD + j * 16], pf[i][j], MLD, wmma::mem_row_major);
            }
    }
    __syncthreads();

    // cell_out = tf32(clip(mix*v + (1-mix)*v_pred)) -> sA (d-major, conflict-free)
    {
        int d = t & 63, g = t >> 6;
        for (int n = g; n < NN; n += 4) {
            float m = smix[n];
            float v = sA[n * MLD + d], p = sB[n * MLD + d];
            sA[n * MLD + d] = wmma::__float_to_tf32(clip3(m * v + (1.f - m) * p));
        }
    }
    __syncthreads();

    // Q = cell_out @ q_w^T -> sB (own rows)
    {
        CFrag qf[2][4];
        #pragma unroll
        for (int i = 0; i < 2; i++)
            #pragma unroll
            for (int j = 0; j < 4; j++) wmma::fill_fragment(qf[i][j], 0.f);
        #pragma unroll
        for (int kk = 0; kk < 8; kk++) {
            AFrag af[2]; BFrag bq[4];
            #pragma unroll
            for (int i = 0; i < 2; i++) wmma::load_matrix_sync(af[i], &sA[(r0w + i * 16) * MLD + kk * 8], MLD);
            #pragma unroll
            for (int j = 0; j < 4; j++) wmma::load_matrix_sync(bq[j], &sQm[(j * 16) * MLD + kk * 8], MLD);
            #pragma unroll
            for (int i = 0; i < 2; i++)
                #pragma unroll
                for (int j = 0; j < 4; j++) wmma::mma_sync(qf[i][j], af[i], bq[j], qf[i][j]);
        }
        #pragma unroll
        for (int i = 0; i < 2; i++)
            #pragma unroll
            for (int j = 0; j < 4; j++)
                wmma::store_matrix_sync(&sB[(r0w + i * 16) * MLD + j * 16], qf[i][j], MLD, wmma::mem_row_major);
    }
    __syncthreads();

    // attention: warp-per-row, 4 dots via shuffle, softmax -> g_w
    {
        float k0a = sKb[lane],        k0b = sKb[lane + 32];
        float k1a = sKb[64 + lane],   k1b = sKb[96 + lane];
        float k2a = sKb[128 + lane],  k2b = sKb[160 + lane];
        float k3a = sKb[192 + lane],  k3b = sKb[224 + lane];
        float qba = sqb[lane], qbb = sqb[lane + 32];
        #pragma unroll
        for (int it = 0; it < 32; it++) {
            int n = it * 8 + w;
            float q0 = sB[n * MLD + lane] + qba;
            float q1 = sB[n * MLD + lane + 32] + qbb;
            float s0 = q0 * k0a + q1 * k0b;
            float s1 = q0 * k1a + q1 * k1b;
            float s2 = q0 * k2a + q1 * k2b;
            float s3 = q0 * k3a + q1 * k3b;
            #pragma unroll
            for (int o = 16; o; o >>= 1) {
                s0 += __shfl_xor_sync(0xffffffffu, s0, o);
                s1 += __shfl_xor_sync(0xffffffffu, s1, o);
                s2 += __shfl_xor_sync(0xffffffffu, s2, o);
                s3 += __shfl_xor_sync(0xffffffffu, s3, o);
            }
            if (lane == 0) {
                s0 *= 0.125f; s1 *= 0.125f; s2 *= 0.125f; s3 *= 0.125f;
                float mx = fmaxf(fmaxf(s0, s1), fmaxf(s2, s3));
                float e0 = expf(s0 - mx), e1 = expf(s1 - mx), e2 = expf(s2 - mx), e3 = expf(s3 - mx);
                float inv = 1.f / (e0 + e1 + e2 + e3);
                ((float4*)(g_w + (size_t)b * CPAD))[n] = make_float4(e0 * inv, e1 * inv, e2 * inv, e3 * inv);
            }
        }
    }
}

// ---------------- launcher ---------------------------------------------------
extern "C" void kernel_launch(void* const* d_in, const int* in_sizes, int n_in,
                              void* d_out, int out_size)
{
    (void)in_sizes; (void)n_in; (void)out_size;
    const float* x      = (const float*)d_in[0];
    const float* W_in   = (const float*)d_in[1];
    const float* b_in   = (const float*)d_in[2];
    const float* adj_w  = (const float*)d_in[3];
    const float* V_slow = (const float*)d_in[5];
    const float* sem    = (const float*)d_in[6];
    const float* mix_w  = (const float*)d_in[7];
    const float* mix_b  = (const float*)d_in[8];
    const float* basis  = (const float*)d_in[9];
    const float* q_w    = (const float*)d_in[10];
    const float* q_b    = (const float*)d_in[11];
    const float* k_w    = (const float*)d_in[12];
    const float* k_b    = (const float*)d_in[13];
    const float* W_out  = (const float*)d_in[14];
    const float* b_out  = (const float*)d_in[15];
    float* out = (float*)d_out;

    cudaFuncSetAttribute(gemm_nt_pipe<false>, cudaFuncAttributeMaxDynamicSharedMemorySize, GEMM_SMEM);
    cudaFuncSetAttribute(gemm_nt_pipe<true>,  cudaFuncAttributeMaxDynamicSharedMemorySize, GEMM_SMEM);
    cudaFuncSetAttribute(middle_kernel, cudaFuncAttributeMaxDynamicSharedMemorySize, MID_SMEM_BYTES);

    void *p_nodes = 0, *p_w = 0, *p_mmat = 0, *p_win2 = 0;
    cudaGetSymbolAddress(&p_nodes, g_nodes);
    cudaGetSymbolAddress(&p_w,     g_w);
    cudaGetSymbolAddress(&p_mmat,  g_mmat);
    cudaGetSymbolAddress(&p_win2,  g_win2);

    prep_kernel<<<1, 256>>>(adj_w, k_w, k_b, basis);
    fold_win_kernel<<<(HH * (FF / 4) + 255) / 256, 256>>>(W_in, b_in);
    mmat_kernel<<<(CC * NN) / 8, 256>>>(W_out, basis);

    // agg = x @ W_in'^T  (adjacency pre-folded)
    gemm_nt_pipe<false><<<dim3(HH / BN, BB / BM), 256, GEMM_SMEM>>>(
        x, (const float*)p_win2, (float*)p_nodes, BB, HH, FF, HH, nullptr);

    middle_kernel<<<BB, 256, MID_SMEM_BYTES>>>(V_slow, sem, mix_w, mix_b, q_w, q_b);

    // logits = w @ Mmat^T + b_out  (direct store to d_out)
    gemm_nt_pipe<true><<<dim3(CPAD / BN, BB / BM), 256, GEMM_SMEM>>>(
        (const float*)p_w, (const float*)p_mmat, out, BB, CC, CPAD, CC, b_out);
}

// round 5
// speedup vs baseline: 1.3238x; 1.3238x over previous
#include <cuda_runtime.h>
#include <mma.h>
#include <math.h>
#include <stdint.h>

using namespace nvcuda;

#define GRIDN 16
#define NN 256
#define DD 64
#define BB 4096
#define FF 512
#define HH 16384
#define CC 1000
#define CPAD 1024

// ---------------- scratch ----------------------------------------------------
__device__ float g_nodes[(size_t)BB * HH];     // agg output of GEMM1
__device__ float g_xr[(size_t)BB * FF];        // x rounded to tf32
__device__ float g_win2[(size_t)HH * FF];      // adj-folded W_in (tf32-rounded)
__device__ float g_bin2[HH];                   // folded b_in
__device__ float g_w[(size_t)BB * CPAD];       // softmax weights (tf32-rounded)
__device__ float g_mmat[(size_t)CC * CPAD];    // folded basis x W_out (tf32-rounded)
__device__ float g_adjw[NN * 4];
__device__ int   g_adjn[NN * 4];
__device__ float g_K[4 * DD];

__device__ __forceinline__ float sigmoidf_(float x) { return 1.0f / (1.0f + expf(-x)); }
__device__ __forceinline__ float clip3(float x) { return fminf(fmaxf(x, -3.0f), 3.0f); }

// ---------------- prep: adjacency rows + K = basis @ k_w^T + k_b ------------
__global__ void prep_kernel(const float* __restrict__ adjw,
                            const float* __restrict__ k_w,
                            const float* __restrict__ k_b,
                            const float* __restrict__ basis)
{
    int t = threadIdx.x;
    int r = t >> 4, c = t & 15;
    int nb[4]; int cnt = 0;
    if (r > 0)         nb[cnt++] = t - GRIDN;
    if (r < GRIDN - 1) nb[cnt++] = t + GRIDN;
    if (c > 0)         nb[cnt++] = t - 1;
    if (c < GRIDN - 1) nb[cnt++] = t + 1;

    float w[4] = {0.f, 0.f, 0.f, 0.f};
    float deg = 0.f;
    for (int j = 0; j < cnt; j++) { w[j] = sigmoidf_(adjw[t * NN + nb[j]]); deg += w[j]; }
    deg = fmaxf(deg, 1e-6f);
    int over = 0;
    for (int j = 0; j < cnt; j++) { w[j] /= deg; if (w[j] > 0.1f) over++; }
    if (over < 1) w[0] = fmaxf(w[0], 0.5f);
    for (int j = 0; j < 4; j++) {
        g_adjw[t * 4 + j] = (j < cnt) ? w[j] : 0.f;
        g_adjn[t * 4 + j] = (j < cnt) ? nb[j] : t;
    }

    int kr = t >> 6, kc = t & 63;
    float acc = k_b[kc];
    for (int d = 0; d < DD; d++) acc += basis[kr * DD + d] * k_w[kc * DD + d];
    g_K[kr * DD + kc] = acc;
}

// ---------------- fold adjacency into W_in / b_in (tf32-round W) ------------
__global__ void fold_win_kernel(const float* __restrict__ W_in, const float* __restrict__ b_in)
{
    int idx = blockIdx.x * blockDim.x + threadIdx.x;
    if (idx >= HH * (FF / 4)) return;
    int row = idx >> 7, c4 = idx & 127;
    int n = row >> 6, d = row & 63;
    float w0 = g_adjw[n * 4 + 0], w1 = g_adjw[n * 4 + 1];
    float w2 = g_adjw[n * 4 + 2], w3 = g_adjw[n * 4 + 3];
    int   r0 = g_adjn[n * 4 + 0] * DD + d, r1 = g_adjn[n * 4 + 1] * DD + d;
    int   r2 = g_adjn[n * 4 + 2] * DD + d, r3 = g_adjn[n * 4 + 3] * DD + d;
    float4 a = ((const float4*)(W_in + (size_t)r0 * FF))[c4];
    float4 b = ((const float4*)(W_in + (size_t)r1 * FF))[c4];
    float4 c = ((const float4*)(W_in + (size_t)r2 * FF))[c4];
    float4 e = ((const float4*)(W_in + (size_t)r3 * FF))[c4];
    float4 o;
    o.x = wmma::__float_to_tf32(w0 * a.x + w1 * b.x + w2 * c.x + w3 * e.x);
    o.y = wmma::__float_to_tf32(w0 * a.y + w1 * b.y + w2 * c.y + w3 * e.y);
    o.z = wmma::__float_to_tf32(w0 * a.z + w1 * b.z + w2 * c.z + w3 * e.z);
    o.w = wmma::__float_to_tf32(w0 * a.w + w1 * b.w + w2 * c.w + w3 * e.w);
    ((float4*)(g_win2 + (size_t)row * FF))[c4] = o;
    if (c4 == 0)
        g_bin2[row] = w0 * b_in[r0] + w1 * b_in[r1] + w2 * b_in[r2] + w3 * b_in[r3];
}

// ---------------- round x to tf32 --------------------------------------------
__global__ void round_x_kernel(const float* __restrict__ x)
{
    int i = blockIdx.x * blockDim.x + threadIdx.x;
    if (i >= BB * FF / 4) return;
    float4 v = ((const float4*)x)[i];
    v.x = wmma::__float_to_tf32(v.x); v.y = wmma::__float_to_tf32(v.y);
    v.z = wmma::__float_to_tf32(v.z); v.w = wmma::__float_to_tf32(v.w);
    ((float4*)g_xr)[i] = v;
}

// ---------------- Mmat[c, n*4+j] = sum_d basis[j,d] * W_out[c, n*64+d] ------
__global__ void mmat_kernel(const float* __restrict__ W_out, const float* __restrict__ basis)
{
    int gw = (blockIdx.x * blockDim.x + threadIdx.x) >> 5;
    int lane = threadIdx.x & 31;
    if (gw >= CC * NN) return;
    const float* row = W_out + (size_t)gw * DD;
    float v0 = row[lane], v1 = row[lane + 32];
    float r0 = v0 * basis[       lane] + v1 * basis[       lane + 32];
    float r1 = v0 * basis[ 64 +  lane] + v1 * basis[ 64 +  lane + 32];
    float r2 = v0 * basis[128 +  lane] + v1 * basis[128 +  lane + 32];
    float r3 = v0 * basis[192 +  lane] + v1 * basis[192 +  lane + 32];
    #pragma unroll
    for (int o = 16; o; o >>= 1) {
        r0 += __shfl_xor_sync(0xffffffffu, r0, o);
        r1 += __shfl_xor_sync(0xffffffffu, r1, o);
        r2 += __shfl_xor_sync(0xffffffffu, r2, o);
        r3 += __shfl_xor_sync(0xffffffffu, r3, o);
    }
    if (lane == 0)
        ((float4*)g_mmat)[gw] = make_float4(
            wmma::__float_to_tf32(r0), wmma::__float_to_tf32(r1),
            wmma::__float_to_tf32(r2), wmma::__float_to_tf32(r3));
}

// ---------------- pipelined NT GEMM (pre-rounded tf32, no in-reg cvt) -------
#define BM 128
#define BN 128
#define BK 32
#define GLDS 36
#define GSTAGE 3
#define GSTRIDE ((BM + BN) * GLDS)
#define GEMM_SMEM (GSTAGE * GSTRIDE * 4)           // 110592 B

__device__ __forceinline__ void g_issue(const float* A, const float* B, float* sm,
                                        int t, int m0, int n0, int K, int Nvalid,
                                        int kt, int s)
{
    int k0 = kt * BK;
    float* dstA0 = sm + s * GSTRIDE;
    float* dstB0 = dstA0 + BM * GLDS;
    #pragma unroll
    for (int i = 0; i < 4; i++) {
        int id = t + i * 256;
        int row = id >> 3, c4 = id & 7;
        const float* gA = A + (size_t)(m0 + row) * K + k0 + c4 * 4;
        unsigned int da = (unsigned int)__cvta_generic_to_shared(dstA0 + row * GLDS + c4 * 4);
        asm volatile("cp.async.cg.shared.global [%0], [%1], 16;\n" :: "r"(da), "l"(gA));
        int brow = n0 + row;
        const float* gB = B + (size_t)brow * K + k0 + c4 * 4;
        unsigned int db = (unsigned int)__cvta_generic_to_shared(dstB0 + row * GLDS + c4 * 4);
        int sz = (brow < Nvalid) ? 16 : 0;
        asm volatile("cp.async.cg.shared.global [%0], [%1], 16, %2;\n" :: "r"(db), "l"(gB), "r"(sz));
    }
    asm volatile("cp.async.commit_group;\n" ::: "memory");
}

template<bool STORE_OUT>
__global__ __launch_bounds__(256, 2) void gemm_nt_pipe(
    const float* __restrict__ A, const float* __restrict__ B, float* __restrict__ C,
    int Nvalid, int K, int ldc, const float* __restrict__ bias)
{
    extern __shared__ float sm[];
    int t = threadIdx.x;
    int m0 = blockIdx.y * BM, n0 = blockIdx.x * BN;
    int w = t >> 5, wm = w & 1, wn = w >> 1;
    int KT = K / BK;

    wmma::fragment<wmma::accumulator, 16, 16, 8, float> acc[4][2];
    #pragma unroll
    for (int i = 0; i < 4; i++)
        #pragma unroll
        for (int j = 0; j < 2; j++) wmma::fill_fragment(acc[i][j], 0.0f);

    g_issue(A, B, sm, t, m0, n0, K, Nvalid, 0, 0);
    g_issue(A, B, sm, t, m0, n0, K, Nvalid, 1, 1);

    for (int kt = 0; kt < KT; kt++) {
        asm volatile("cp.async.wait_group 1;\n" ::: "memory");
        __syncthreads();
        if (kt + 2 < KT)
            g_issue(A, B, sm, t, m0, n0, K, Nvalid, kt + 2, (kt + 2) % GSTAGE);

        const float* sa = sm + (kt % GSTAGE) * GSTRIDE;
        const float* sb = sa + BM * GLDS;
        #pragma unroll
        for (int kk = 0; kk < BK / 8; kk++) {
            wmma::fragment<wmma::matrix_a, 16, 16, 8, wmma::precision::tf32, wmma::row_major> af[4];
            wmma::fragment<wmma::matrix_b, 16, 16, 8, wmma::precision::tf32, wmma::col_major> bf[2];
            #pragma unroll
            for (int i = 0; i < 4; i++)
                wmma::load_matrix_sync(af[i], sa + (wm * 64 + i * 16) * GLDS + kk * 8, GLDS);
            #pragma unroll
            for (int j = 0; j < 2; j++)
                wmma::load_matrix_sync(bf[j], sb + (wn * 32 + j * 16) * GLDS + kk * 8, GLDS);
            #pragma unroll
            for (int i = 0; i < 4; i++)
                #pragma unroll
                for (int j = 0; j < 2; j++)
                    wmma::mma_sync(acc[i][j], af[i], bf[j], acc[i][j]);
        }
    }

    if (STORE_OUT) {
        __syncthreads();
        float* tile = sm;   // 128 x 132 staging
        #pragma unroll
        for (int i = 0; i < 4; i++)
            #pragma unroll
            for (int j = 0; j < 2; j++)
                wmma::store_matrix_sync(tile + (wm * 64 + i * 16) * 132 + wn * 32 + j * 16,
                                        acc[i][j], 132, wmma::mem_row_major);
        __syncthreads();
        for (int idx = t; idx < BM * BN; idx += 256) {
            int r = idx >> 7, c = idx & 127;
            int col = n0 + c;
            if (col < Nvalid)
                C[(size_t)(m0 + r) * ldc + col] = tile[r * 132 + c] + bias[col];
        }
    } else {
        #pragma unroll
        for (int i = 0; i < 4; i++)
            #pragma unroll
            for (int j = 0; j < 2; j++)
                wmma::store_matrix_sync(C + (size_t)(m0 + wm * 64 + i * 16) * ldc + n0 + wn * 32 + j * 16,
                                        acc[i][j], ldc, wmma::mem_row_major);
    }
}

// ---------------- fused middle (R2-proven body, agg pre-folded) -------------
#define MLD 68
constexpr int MID_SMEM_FLOATS = 256 * MLD * 2 + 64 * MLD * 3 + 256 + 256 + 64 + 64;
constexpr int MID_SMEM_BYTES  = MID_SMEM_FLOATS * 4;

__global__ __launch_bounds__(256) void middle_kernel(
    const float* __restrict__ V_slow, const float* __restrict__ sem_mem,
    const float* __restrict__ mix_w, const float* __restrict__ mix_b,
    const float* __restrict__ q_w, const float* __restrict__ q_b)
{
    extern __shared__ float smem_[];
    float* sA   = smem_;               // 256*68 (y_pred, v_pred, cell_out)
    float* sB   = sA + 256 * MLD;      // 256*68 (agg, v, Q)
    float* sV   = sB + 256 * MLD;      // 64*68
    float* sS   = sV + 64 * MLD;       // 64*68
    float* sQm  = sS + 64 * MLD;       // 64*68
    float* smix = sQm + 64 * MLD;      // 256
    float* sKb  = smix + 256;          // 256
    float* sqb  = sKb + 256;           // 64
    float* smw  = sqb + 64;            // 64

    int b = blockIdx.x;
    int t = threadIdx.x;

    for (int i = t; i < 64 * 64; i += 256) {
        int r = i >> 6, c2 = i & 63;
        sV[r * MLD + c2]  = wmma::__float_to_tf32(V_slow[i]);
        sS[r * MLD + c2]  = wmma::__float_to_tf32(sem_mem[i]);
        sQm[r * MLD + c2] = wmma::__float_to_tf32(q_w[i]);
    }
    if (t < 64) { sqb[t] = q_b[t]; smw[t] = mix_w[t]; }
    sKb[t] = g_K[t];

    // agg (pre-folded) + bias -> sB (tf32)
    {
        const float4* np_ = (const float4*)(g_nodes + (size_t)b * HH);
        const float4* bp_ = (const float4*)g_bin2;
        for (int i = t; i < HH / 4; i += 256) {
            float4 v = np_[i], bb = bp_[i];
            int n = i >> 4, d = (i & 15) << 2;
            float* dst = &sB[n * MLD + d];
            dst[0] = wmma::__float_to_tf32(v.x + bb.x);
            dst[1] = wmma::__float_to_tf32(v.y + bb.y);
            dst[2] = wmma::__float_to_tf32(v.z + bb.z);
            dst[3] = wmma::__float_to_tf32(v.w + bb.w);
        }
    }
    __syncthreads();

    int w = t >> 5;
    int r0w = w * 32;

    typedef wmma::fragment<wmma::matrix_a, 16, 16, 8, wmma::precision::tf32, wmma::row_major> AFrag;
    typedef wmma::fragment<wmma::matrix_b, 16, 16, 8, wmma::precision::tf32, wmma::col_major> BFrag;
    typedef wmma::fragment<wmma::accumulator, 16, 16, 8, float> CFrag;

    // v = clip(agg @ V^T), y_pred = clip(agg @ S^T)
    {
        CFrag vf[2][4], yf[2][4];
        #pragma unroll
        for (int i = 0; i < 2; i++)
            #pragma unroll
            for (int j = 0; j < 4; j++) { wmma::fill_fragment(vf[i][j], 0.f); wmma::fill_fragment(yf[i][j], 0.f); }
        #pragma unroll
        for (int kk = 0; kk < 8; kk++) {
            AFrag af[2]; BFrag bv[4], bs[4];
            #pragma unroll
            for (int i = 0; i < 2; i++) wmma::load_matrix_sync(af[i], &sB[(r0w + i * 16) * MLD + kk * 8], MLD);
            #pragma unroll
            for (int j = 0; j < 4; j++) {
                wmma::load_matrix_sync(bv[j], &sV[(j * 16) * MLD + kk * 8], MLD);
                wmma::load_matrix_sync(bs[j], &sS[(j * 16) * MLD + kk * 8], MLD);
            }
            #pragma unroll
            for (int i = 0; i < 2; i++)
                #pragma unroll
                for (int j = 0; j < 4; j++) {
                    wmma::mma_sync(vf[i][j], af[i], bv[j], vf[i][j]);
                    wmma::mma_sync(yf[i][j], af[i], bs[j], yf[i][j]);
                }
        }
        #pragma unroll
        for (int i = 0; i < 2; i++)
            #pragma unroll
            for (int j = 0; j < 4; j++)
                for (int e = 0; e < vf[i][j].num_elements; e++) {
                    vf[i][j].x[e] = clip3(vf[i][j].x[e]);
                    yf[i][j].x[e] = clip3(yf[i][j].x[e]);
                }
        #pragma unroll
        for (int i = 0; i < 2; i++)
            #pragma unroll
            for (int j = 0; j < 4; j++)
                wmma::store_matrix_sync(&sA[(r0w + i * 16) * MLD + j * 16], yf[i][j], MLD, wmma::mem_row_major);
        __syncthreads();
        #pragma unroll
        for (int i = 0; i < 2; i++)
            #pragma unroll
            for (int j = 0; j < 4; j++)
                wmma::store_matrix_sync(&sB[(r0w + i * 16) * MLD + j * 16], vf[i][j], MLD, wmma::mem_row_major);
    }
    __syncthreads();

    // mix = sigmoid(v . mix_w + mix_b); y_pred -> tf32 in place (per-thread)
    {
        int n = t;
        float m = mix_b[0];
        #pragma unroll
        for (int d = 0; d < DD; d++) m += sB[n * MLD + d] * smw[d];
        smix[n] = sigmoidf_(m);
        float* ya = &sA[n * MLD];
        #pragma unroll
        for (int d = 0; d < DD; d++) ya[d] = wmma::__float_to_tf32(ya[d]);
    }
    __syncthreads();

    // v_pred = clip(y_pred @ V^T) -> sA
    {
        CFrag pf[2][4];
        #pragma unroll
        for (int i = 0; i < 2; i++)
            #pragma unroll
            for (int j = 0; j < 4; j++) wmma::fill_fragment(pf[i][j], 0.f);
        #pragma unroll
        for (int kk = 0; kk < 8; kk++) {
            AFrag af[2]; BFrag bv[4];
            #pragma unroll
            for (int i = 0; i < 2; i++) wmma::load_matrix_sync(af[i], &sA[(r0w + i * 16) * MLD + kk * 8], MLD);
            #pragma unroll
            for (int j = 0; j < 4; j++) wmma::load_matrix_sync(bv[j], &sV[(j * 16) * MLD + kk * 8], MLD);
            #pragma unroll
            for (int i = 0; i < 2; i++)
                #pragma unroll
                for (int j = 0; j < 4; j++) wmma::mma_sync(pf[i][j], af[i], bv[j], pf[i][j]);
        }
        #pragma unroll
        for (int i = 0; i < 2; i++)
            #pragma unroll
            for (int j = 0; j < 4; j++)
                for (int e = 0; e < pf[i][j].num_elements; e++) pf[i][j].x[e] = clip3(pf[i][j].x[e]);
        __syncthreads();
        #pragma unroll
        for (int i = 0; i < 2; i++)
            #pragma unroll
            for (int j = 0; j < 4; j++)
                wmma::store_matrix_sync(&sA[(r0w + i * 16) * MLD + j * 16], pf[i][j], MLD, wmma::mem_row_major);
    }
    __syncthreads();

    // cell_out = tf32(clip(mix*v + (1-mix)*v_pred)) -> sA (per-thread)
    {
        int n = t;
        float m = smix[n];
        float* va = &sB[n * MLD];
        float* pa = &sA[n * MLD];
        #pragma unroll
        for (int d = 0; d < DD; d++)
            pa[d] = wmma::__float_to_tf32(clip3(m * va[d] + (1.f - m) * pa[d]));
    }
    __syncthreads();

    // Q = cell_out @ q_w^T -> sB
    {
        CFrag qf[2][4];
        #pragma unroll
        for (int i = 0; i < 2; i++)
            #pragma unroll
            for (int j = 0; j < 4; j++) wmma::fill_fragment(qf[i][j], 0.f);
        #pragma unroll
        for (int kk = 0; kk < 8; kk++) {
            AFrag af[2]; BFrag bq[4];
            #pragma unroll
            for (int i = 0; i < 2; i++) wmma::load_matrix_sync(af[i], &sA[(r0w + i * 16) * MLD + kk * 8], MLD);
            #pragma unroll
            for (int j = 0; j < 4; j++) wmma::load_matrix_sync(bq[j], &sQm[(j * 16) * MLD + kk * 8], MLD);
            #pragma unroll
            for (int i = 0; i < 2; i++)
                #pragma unroll
                for (int j = 0; j < 4; j++) wmma::mma_sync(qf[i][j], af[i], bq[j], qf[i][j]);
        }
        #pragma unroll
        for (int i = 0; i < 2; i++)
            #pragma unroll
            for (int j = 0; j < 4; j++)
                wmma::store_matrix_sync(&sB[(r0w + i * 16) * MLD + j * 16], qf[i][j], MLD, wmma::mem_row_major);
    }
    __syncthreads();

    // attention: per-thread over 4 basis vectors -> softmax -> g_w (tf32-rounded)
    {
        int n = t;
        float q[DD];
        #pragma unroll
        for (int d = 0; d < DD; d++) q[d] = sB[n * MLD + d] + sqb[d];
        float s0 = 0.f, s1 = 0.f, s2 = 0.f, s3 = 0.f;
        #pragma unroll
        for (int d = 0; d < DD; d++) {
            s0 += q[d] * sKb[d];        s1 += q[d] * sKb[64 + d];
            s2 += q[d] * sKb[128 + d];  s3 += q[d] * sKb[192 + d];
        }
        s0 *= 0.125f; s1 *= 0.125f; s2 *= 0.125f; s3 *= 0.125f;
        float mx = fmaxf(fmaxf(s0, s1), fmaxf(s2, s3));
        float e0 = expf(s0 - mx), e1 = expf(s1 - mx), e2 = expf(s2 - mx), e3 = expf(s3 - mx);
        float inv = 1.f / (e0 + e1 + e2 + e3);
        ((float4*)(g_w + (size_t)b * CPAD))[n] = make_float4(
            wmma::__float_to_tf32(e0 * inv), wmma::__float_to_tf32(e1 * inv),
            wmma::__float_to_tf32(e2 * inv), wmma::__float_to_tf32(e3 * inv));
    }
}

// ---------------- launcher ---------------------------------------------------
extern "C" void kernel_launch(void* const* d_in, const int* in_sizes, int n_in,
                              void* d_out, int out_size)
{
    (void)in_sizes; (void)n_in; (void)out_size;
    const float* x      = (const float*)d_in[0];
    const float* W_in   = (const float*)d_in[1];
    const float* b_in   = (const float*)d_in[2];
    const float* adj_w  = (const float*)d_in[3];
    const float* V_slow = (const float*)d_in[5];
    const float* sem    = (const float*)d_in[6];
    const float* mix_w  = (const float*)d_in[7];
    const float* mix_b  = (const float*)d_in[8];
    const float* basis  = (const float*)d_in[9];
    const float* q_w    = (const float*)d_in[10];
    const float* q_b    = (const float*)d_in[11];
    const float* k_w    = (const float*)d_in[12];
    const float* k_b    = (const float*)d_in[13];
    const float* W_out  = (const float*)d_in[14];
    const float* b_out  = (const float*)d_in[15];
    float* out = (float*)d_out;

    cudaFuncSetAttribute(gemm_nt_pipe<false>, cudaFuncAttributeMaxDynamicSharedMemorySize, GEMM_SMEM);
    cudaFuncSetAttribute(gemm_nt_pipe<true>,  cudaFuncAttributeMaxDynamicSharedMemorySize, GEMM_SMEM);
    cudaFuncSetAttribute(middle_kernel, cudaFuncAttributeMaxDynamicSharedMemorySize, MID_SMEM_BYTES);

    void *p_nodes = 0, *p_w = 0, *p_mmat = 0, *p_win2 = 0, *p_xr = 0;
    cudaGetSymbolAddress(&p_nodes, g_nodes);
    cudaGetSymbolAddress(&p_w,     g_w);
    cudaGetSymbolAddress(&p_mmat,  g_mmat);
    cudaGetSymbolAddress(&p_win2,  g_win2);
    cudaGetSymbolAddress(&p_xr,    g_xr);

    prep_kernel<<<1, 256>>>(adj_w, k_w, k_b, basis);
    fold_win_kernel<<<(HH * (FF / 4) + 255) / 256, 256>>>(W_in, b_in);
    round_x_kernel<<<(BB * FF / 4 + 255) / 256, 256>>>(x);
    mmat_kernel<<<(CC * NN) / 8, 256>>>(W_out, basis);

    // agg = xr @ W_in'^T  (all inputs pre-rounded to tf32)
    gemm_nt_pipe<false><<<dim3(HH / BN, BB / BM), 256, GEMM_SMEM>>>(
        (const float*)p_xr, (const float*)p_win2, (float*)p_nodes, HH, FF, HH, nullptr);

    middle_kernel<<<BB, 256, MID_SMEM_BYTES>>>(V_slow, sem, mix_w, mix_b, q_w, q_b);

    // logits = w @ Mmat^T + b_out  (direct store to d_out)
    gemm_nt_pipe<true><<<dim3(CPAD / BN, BB / BM), 256, GEMM_SMEM>>>(
        (const float*)p_w, (const float*)p_mmat, out, CC, CPAD, CC, b_out);
}